// round 10
// baseline (speedup 1.0000x reference)
#include <cuda_runtime.h>
#include <math.h>

#define LAMBDA 1.5f
#define B_SZ 32
#define N_SZ 2048
#define HID 256
#define THREADS 256
#define WARPS_PER_BLOCK 8
#define ROWS_PER_BLOCK (WARPS_PER_BLOCK * 2)   // 2 rows per warp, interleaved

// ---------------------------------------------------------------------------
// R9 + dual-row warps: each warp streams TWO Y-rows (n, n+8) in one fused
// k-loop -> 4 gmem streams/warp, ~2x in-flight LDG.128. Occupancy traded
// down (launch_bounds(256,4), ~50%) for register headroom; R2/R3 showed occ
// in the 49-73% range is not the binding factor, per-warp MLP is.
// Block count halves -> half the x-staging traffic and start bubbles.
// ---------------------------------------------------------------------------
__global__ __launch_bounds__(THREADS, 4) void fused_kernel(
    const float* __restrict__ Yr, const float* __restrict__ Yi,
    const float* __restrict__ xr, const float* __restrict__ xi,
    const float* __restrict__ xpr, const float* __restrict__ xpi,
    const float* __restrict__ d3w, const float* __restrict__ d3b,
    const float* __restrict__ w1, const float* __restrict__ b1,
    const float* __restrict__ w2, const float* __restrict__ b2,
    float* __restrict__ out) {

    __shared__ float sxr[N_SZ];
    __shared__ float sxi[N_SZ];
    __shared__ float sw1[HID];
    __shared__ float sb1[HID];
    __shared__ float sw2[HID];

    const int tid = threadIdx.x;
    const int b = blockIdx.y;

    // ---- Stage x vectors for this batch + MLP weights into shared ----
    {
        const float4* xr4 = (const float4*)(xr + (size_t)b * N_SZ);
        const float4* xi4 = (const float4*)(xi + (size_t)b * N_SZ);
        float4* sxr4 = (float4*)sxr;
        float4* sxi4 = (float4*)sxi;
        #pragma unroll
        for (int k = tid; k < N_SZ / 4; k += THREADS) {
            sxr4[k] = xr4[k];
            sxi4[k] = xi4[k];
        }
        if (tid < HID) {
            sw1[tid] = w1[tid];
            sb1[tid] = b1[tid];
            sw2[tid] = w2[tid];
        }
    }
    __syncthreads();

    const int wid = tid >> 5;
    const int lid = tid & 31;
    const int n0 = blockIdx.x * ROWS_PER_BLOCK + wid;      // first row
    const int n1 = n0 + WARPS_PER_BLOCK;                   // second row

    const size_t base0 = (((size_t)b * N_SZ) + n0) * N_SZ;
    const size_t base1 = (((size_t)b * N_SZ) + n1) * N_SZ;
    const float4* yr0 = (const float4*)(Yr + base0);
    const float4* yi0 = (const float4*)(Yi + base0);
    const float4* yr1 = (const float4*)(Yr + base1);
    const float4* yi1 = (const float4*)(Yi + base1);
    const float4* sxr4 = (const float4*)sxr;
    const float4* sxi4 = (const float4*)sxi;

    // Hoist scalar epilogue params (latency hidden under the stream)
    const float dw  = d3w[0];
    const float db  = d3b[0];
    const float b2v = b2[0];
    const size_t idx0 = (size_t)b * N_SZ + n0;
    const size_t idx1 = (size_t)b * N_SZ + n1;
    const float xpr0 = xpr[idx0], xpi0 = xpi[idx0];
    const float xpr1 = xpr[idx1], xpi1 = xpi[idx1];

    // ---- Main streaming loop: 2 rows x 4 dots + |x|^2, all fused ----
    float rr0 = 0.f, ii0 = 0.f, ri0 = 0.f, ir0 = 0.f;
    float rr1 = 0.f, ii1 = 0.f, ri1 = 0.f, ir1 = 0.f;
    float ss = 0.f;

    #pragma unroll 8
    for (int k = lid; k < N_SZ / 4; k += 32) {
        float4 a0 = yr0[k];
        float4 c0 = yi0[k];
        float4 a1 = yr1[k];
        float4 c1 = yi1[k];
        float4 u = sxr4[k];
        float4 v = sxi4[k];

        rr0 = fmaf(a0.x, u.x, rr0); rr0 = fmaf(a0.y, u.y, rr0);
        rr0 = fmaf(a0.z, u.z, rr0); rr0 = fmaf(a0.w, u.w, rr0);
        ii0 = fmaf(c0.x, v.x, ii0); ii0 = fmaf(c0.y, v.y, ii0);
        ii0 = fmaf(c0.z, v.z, ii0); ii0 = fmaf(c0.w, v.w, ii0);
        ri0 = fmaf(a0.x, v.x, ri0); ri0 = fmaf(a0.y, v.y, ri0);
        ri0 = fmaf(a0.z, v.z, ri0); ri0 = fmaf(a0.w, v.w, ri0);
        ir0 = fmaf(c0.x, u.x, ir0); ir0 = fmaf(c0.y, u.y, ir0);
        ir0 = fmaf(c0.z, u.z, ir0); ir0 = fmaf(c0.w, u.w, ir0);

        rr1 = fmaf(a1.x, u.x, rr1); rr1 = fmaf(a1.y, u.y, rr1);
        rr1 = fmaf(a1.z, u.z, rr1); rr1 = fmaf(a1.w, u.w, rr1);
        ii1 = fmaf(c1.x, v.x, ii1); ii1 = fmaf(c1.y, v.y, ii1);
        ii1 = fmaf(c1.z, v.z, ii1); ii1 = fmaf(c1.w, v.w, ii1);
        ri1 = fmaf(a1.x, v.x, ri1); ri1 = fmaf(a1.y, v.y, ri1);
        ri1 = fmaf(a1.z, v.z, ri1); ri1 = fmaf(a1.w, v.w, ri1);
        ir1 = fmaf(c1.x, u.x, ir1); ir1 = fmaf(c1.y, u.y, ir1);
        ir1 = fmaf(c1.z, u.z, ir1); ir1 = fmaf(c1.w, u.w, ir1);

        ss = fmaf(u.x, u.x, ss); ss = fmaf(u.y, u.y, ss);
        ss = fmaf(u.z, u.z, ss); ss = fmaf(u.w, u.w, ss);
        ss = fmaf(v.x, v.x, ss); ss = fmaf(v.y, v.y, ss);
        ss = fmaf(v.z, v.z, ss); ss = fmaf(v.w, v.w, ss);
    }

    // butterfly reduce all nine accumulators
    #pragma unroll
    for (int off = 16; off > 0; off >>= 1) {
        rr0 += __shfl_xor_sync(0xFFFFFFFFu, rr0, off);
        ii0 += __shfl_xor_sync(0xFFFFFFFFu, ii0, off);
        ri0 += __shfl_xor_sync(0xFFFFFFFFu, ri0, off);
        ir0 += __shfl_xor_sync(0xFFFFFFFFu, ir0, off);
        rr1 += __shfl_xor_sync(0xFFFFFFFFu, rr1, off);
        ii1 += __shfl_xor_sync(0xFFFFFFFFu, ii1, off);
        ri1 += __shfl_xor_sync(0xFFFFFFFFu, ri1, off);
        ir1 += __shfl_xor_sync(0xFFFFFFFFu, ir1, off);
        ss  += __shfl_xor_sync(0xFFFFFFFFu, ss,  off);
    }

    const float sc = -(LAMBDA * LAMBDA) * (1.0f - ss / (float)N_SZ);

    // ---- Epilogue row 0 ----
    float x1r0 = fmaf(LAMBDA * (rr0 - ii0), dw, db);
    float x1i0 = fmaf(LAMBDA * (ri0 + ir0), dw, db);
    x1r0 = fmaf(sc, xpr0, x1r0);
    x1i0 = fmaf(sc, xpi0, x1i0);
    const float xabs0 = sqrtf(x1r0 * x1r0 + x1i0 * x1i0);

    // ---- Epilogue row 1 ----
    float x1r1 = fmaf(LAMBDA * (rr1 - ii1), dw, db);
    float x1i1 = fmaf(LAMBDA * (ri1 + ir1), dw, db);
    x1r1 = fmaf(sc, xpr1, x1r1);
    x1i1 = fmaf(sc, xpi1, x1i1);
    const float xabs1 = sqrtf(x1r1 * x1r1 + x1i1 * x1i1);

    // MLP for both rows (interleaved, shared weight loads)
    float p0 = 0.f, p1 = 0.f;
    #pragma unroll
    for (int j = lid; j < HID; j += 32) {
        const float w1j = sw1[j];
        const float b1j = sb1[j];
        const float w2j = sw2[j];
        float h0 = fmaxf(fmaf(xabs0, w1j, b1j), 0.f);
        float h1 = fmaxf(fmaf(xabs1, w1j, b1j), 0.f);
        p0 = fmaf(h0, w2j, p0);
        p1 = fmaf(h1, w2j, p1);
    }
    #pragma unroll
    for (int off = 16; off > 0; off >>= 1) {
        p0 += __shfl_xor_sync(0xFFFFFFFFu, p0, off);
        p1 += __shfl_xor_sync(0xFFFFFFFFu, p1, off);
    }

    if (lid == 0) {
        float g0 = tanhf(p0 + b2v);
        float q0 = g0 / fmaxf(xabs0, 1e-12f);
        out[idx0] = x1r0 * q0;
        out[(size_t)B_SZ * N_SZ + idx0] = x1i0 * q0;

        float g1 = tanhf(p1 + b2v);
        float q1 = g1 / fmaxf(xabs1, 1e-12f);
        out[idx1] = x1r1 * q1;
        out[(size_t)B_SZ * N_SZ + idx1] = x1i1 * q1;
    }
}

extern "C" void kernel_launch(void* const* d_in, const int* in_sizes, int n_in,
                              void* d_out, int out_size) {
    const float* Yr  = (const float*)d_in[0];
    const float* Yi  = (const float*)d_in[1];
    const float* xr  = (const float*)d_in[2];
    const float* xi  = (const float*)d_in[3];
    const float* xpr = (const float*)d_in[4];
    const float* xpi = (const float*)d_in[5];
    const float* d3w = (const float*)d_in[6];
    const float* d3b = (const float*)d_in[7];
    const float* w1  = (const float*)d_in[8];
    const float* b1  = (const float*)d_in[9];
    const float* w2  = (const float*)d_in[10];
    const float* b2  = (const float*)d_in[11];
    float* out = (float*)d_out;

    dim3 grid(N_SZ / ROWS_PER_BLOCK, B_SZ);
    fused_kernel<<<grid, THREADS>>>(Yr, Yi, xr, xi, xpr, xpi,
                                    d3w, d3b, w1, b1, w2, b2, out);
}

// round 11
// speedup vs baseline: 1.1753x; 1.1753x over previous
#include <cuda_runtime.h>
#include <math.h>

#define LAMBDA 1.5f
#define B_SZ 32
#define N_SZ 2048
#define HID 256
#define THREADS 256
#define WARPS_PER_BLOCK 8   // one output row per warp

// ---------------------------------------------------------------------------
// R9 (best: 154.1us, DRAM 89.0%) + cross-barrier Y prefetch: the first
// k-iteration's two LDG.128 are issued BEFORE the x-staging phase, so their
// ~600-cycle DRAM latency overlaps staging + __syncthreads instead of
// stacking a dead window on every one of the 8192 block starts.
// Everything else identical: 256 thr / 8 warps / 1 row per warp, |x|^2 fused
// in-loop, full unroll, plain LDG, launch_bounds(256,6).
// ---------------------------------------------------------------------------
__global__ __launch_bounds__(THREADS, 6) void fused_kernel(
    const float* __restrict__ Yr, const float* __restrict__ Yi,
    const float* __restrict__ xr, const float* __restrict__ xi,
    const float* __restrict__ xpr, const float* __restrict__ xpi,
    const float* __restrict__ d3w, const float* __restrict__ d3b,
    const float* __restrict__ w1, const float* __restrict__ b1,
    const float* __restrict__ w2, const float* __restrict__ b2,
    float* __restrict__ out) {

    __shared__ float sxr[N_SZ];
    __shared__ float sxi[N_SZ];
    __shared__ float sw1[HID];
    __shared__ float sb1[HID];
    __shared__ float sw2[HID];

    const int tid = threadIdx.x;
    const int b = blockIdx.y;
    const int wid = tid >> 5;
    const int lid = tid & 31;
    const int n = blockIdx.x * WARPS_PER_BLOCK + wid;

    const size_t row_base = (((size_t)b * N_SZ) + n) * N_SZ;
    const float4* yr4 = (const float4*)(Yr + row_base);
    const float4* yi4 = (const float4*)(Yi + row_base);

    // ---- PREFETCH: first k-iteration's Y loads, issued before staging ----
    const float4 a_p = yr4[lid];
    const float4 c_p = yi4[lid];

    // Hoist scalar epilogue params (also overlap the staging phase)
    const float dw  = d3w[0];
    const float db  = d3b[0];
    const float b2v = b2[0];
    const size_t idx = (size_t)b * N_SZ + n;
    const float xpr_v = xpr[idx];
    const float xpi_v = xpi[idx];

    // ---- Stage x vectors for this batch + MLP weights into shared ----
    {
        const float4* xr4 = (const float4*)(xr + (size_t)b * N_SZ);
        const float4* xi4 = (const float4*)(xi + (size_t)b * N_SZ);
        float4* sxr4s = (float4*)sxr;
        float4* sxi4s = (float4*)sxi;
        #pragma unroll
        for (int k = tid; k < N_SZ / 4; k += THREADS) {
            sxr4s[k] = xr4[k];
            sxi4s[k] = xi4[k];
        }
        if (tid < HID) {
            sw1[tid] = w1[tid];
            sb1[tid] = b1[tid];
            sw2[tid] = w2[tid];
        }
    }
    __syncthreads();

    const float4* sxr4 = (const float4*)sxr;
    const float4* sxi4 = (const float4*)sxi;

    float rr = 0.f, ii = 0.f, ri = 0.f, ir = 0.f, ss = 0.f;

    // ---- Consume the prefetched first iteration (k = lid) ----
    {
        float4 u = sxr4[lid];
        float4 v = sxi4[lid];
        rr = fmaf(a_p.x, u.x, rr); rr = fmaf(a_p.y, u.y, rr);
        rr = fmaf(a_p.z, u.z, rr); rr = fmaf(a_p.w, u.w, rr);
        ii = fmaf(c_p.x, v.x, ii); ii = fmaf(c_p.y, v.y, ii);
        ii = fmaf(c_p.z, v.z, ii); ii = fmaf(c_p.w, v.w, ii);
        ri = fmaf(a_p.x, v.x, ri); ri = fmaf(a_p.y, v.y, ri);
        ri = fmaf(a_p.z, v.z, ri); ri = fmaf(a_p.w, v.w, ri);
        ir = fmaf(c_p.x, u.x, ir); ir = fmaf(c_p.y, u.y, ir);
        ir = fmaf(c_p.z, u.z, ir); ir = fmaf(c_p.w, u.w, ir);
        ss = fmaf(u.x, u.x, ss); ss = fmaf(u.y, u.y, ss);
        ss = fmaf(u.z, u.z, ss); ss = fmaf(u.w, u.w, ss);
        ss = fmaf(v.x, v.x, ss); ss = fmaf(v.y, v.y, ss);
        ss = fmaf(v.z, v.z, ss); ss = fmaf(v.w, v.w, ss);
    }

    // ---- Remaining 15 iterations, fully unrolled ----
    #pragma unroll 15
    for (int k = lid + 32; k < N_SZ / 4; k += 32) {
        float4 a = yr4[k];
        float4 c = yi4[k];
        float4 u = sxr4[k];
        float4 v = sxi4[k];
        rr = fmaf(a.x, u.x, rr); rr = fmaf(a.y, u.y, rr);
        rr = fmaf(a.z, u.z, rr); rr = fmaf(a.w, u.w, rr);
        ii = fmaf(c.x, v.x, ii); ii = fmaf(c.y, v.y, ii);
        ii = fmaf(c.z, v.z, ii); ii = fmaf(c.w, v.w, ii);
        ri = fmaf(a.x, v.x, ri); ri = fmaf(a.y, v.y, ri);
        ri = fmaf(a.z, v.z, ri); ri = fmaf(a.w, v.w, ri);
        ir = fmaf(c.x, u.x, ir); ir = fmaf(c.y, u.y, ir);
        ir = fmaf(c.z, u.z, ir); ir = fmaf(c.w, u.w, ir);
        ss = fmaf(u.x, u.x, ss); ss = fmaf(u.y, u.y, ss);
        ss = fmaf(u.z, u.z, ss); ss = fmaf(u.w, u.w, ss);
        ss = fmaf(v.x, v.x, ss); ss = fmaf(v.y, v.y, ss);
        ss = fmaf(v.z, v.z, ss); ss = fmaf(v.w, v.w, ss);
    }

    // butterfly reduce all five accumulators -> every lane has full sums
    #pragma unroll
    for (int off = 16; off > 0; off >>= 1) {
        rr += __shfl_xor_sync(0xFFFFFFFFu, rr, off);
        ii += __shfl_xor_sync(0xFFFFFFFFu, ii, off);
        ri += __shfl_xor_sync(0xFFFFFFFFu, ri, off);
        ir += __shfl_xor_sync(0xFFFFFFFFu, ir, off);
        ss += __shfl_xor_sync(0xFFFFFFFFu, ss, off);
    }

    // ---- Epilogue (per-warp; no cross-warp communication needed) ----
    const float sc = -(LAMBDA * LAMBDA) * (1.0f - ss / (float)N_SZ);

    float x1r = fmaf(LAMBDA * (rr - ii), dw, db);
    float x1i = fmaf(LAMBDA * (ri + ir), dw, db);
    x1r = fmaf(sc, xpr_v, x1r);
    x1i = fmaf(sc, xpi_v, x1i);

    const float xabs = sqrtf(x1r * x1r + x1i * x1i);

    // MLP: 256 hidden units, 8 per lane
    float partial = 0.f;
    #pragma unroll
    for (int j = lid; j < HID; j += 32) {
        float h = fmaxf(fmaf(xabs, sw1[j], sb1[j]), 0.f);
        partial = fmaf(h, sw2[j], partial);
    }
    #pragma unroll
    for (int off = 16; off > 0; off >>= 1)
        partial += __shfl_xor_sync(0xFFFFFFFFu, partial, off);

    if (lid == 0) {
        float g = tanhf(partial + b2v);
        float q = g / fmaxf(xabs, 1e-12f);
        out[idx] = x1r * q;                          // real part
        out[(size_t)B_SZ * N_SZ + idx] = x1i * q;    // imag part
    }
}

extern "C" void kernel_launch(void* const* d_in, const int* in_sizes, int n_in,
                              void* d_out, int out_size) {
    const float* Yr  = (const float*)d_in[0];
    const float* Yi  = (const float*)d_in[1];
    const float* xr  = (const float*)d_in[2];
    const float* xi  = (const float*)d_in[3];
    const float* xpr = (const float*)d_in[4];
    const float* xpi = (const float*)d_in[5];
    const float* d3w = (const float*)d_in[6];
    const float* d3b = (const float*)d_in[7];
    const float* w1  = (const float*)d_in[8];
    const float* b1  = (const float*)d_in[9];
    const float* w2  = (const float*)d_in[10];
    const float* b2  = (const float*)d_in[11];
    float* out = (float*)d_out;

    dim3 grid(N_SZ / WARPS_PER_BLOCK, B_SZ);
    fused_kernel<<<grid, THREADS>>>(Yr, Yi, xr, xi, xpr, xpi,
                                    d3w, d3b, w1, b1, w2, b2, out);
}

// round 12
// speedup vs baseline: 1.1893x; 1.0119x over previous
#include <cuda_runtime.h>
#include <cuda_pipeline.h>
#include <math.h>

#define LAMBDA 1.5f
#define B_SZ 32
#define N_SZ 2048
#define HID 256
#define THREADS 256
#define WARPS_PER_BLOCK 8   // one output row per warp

// ---------------------------------------------------------------------------
// R11 (best: 152.1us, DRAM 89.9%) + cp.async x-staging + 2-deep Y prefetch:
// staging no longer round-trips through registers (LDGSTS), freeing budget
// to hold TWO prefetched k-iterations (4x LDG.128) across the barrier, so
// ~1200 cycles of DRAM latency overlap the block prologue.
// ---------------------------------------------------------------------------
__global__ __launch_bounds__(THREADS, 6) void fused_kernel(
    const float* __restrict__ Yr, const float* __restrict__ Yi,
    const float* __restrict__ xr, const float* __restrict__ xi,
    const float* __restrict__ xpr, const float* __restrict__ xpi,
    const float* __restrict__ d3w, const float* __restrict__ d3b,
    const float* __restrict__ w1, const float* __restrict__ b1,
    const float* __restrict__ w2, const float* __restrict__ b2,
    float* __restrict__ out) {

    __shared__ float sxr[N_SZ];
    __shared__ float sxi[N_SZ];
    __shared__ float sw1[HID];
    __shared__ float sb1[HID];
    __shared__ float sw2[HID];

    const int tid = threadIdx.x;
    const int b = blockIdx.y;
    const int wid = tid >> 5;
    const int lid = tid & 31;
    const int n = blockIdx.x * WARPS_PER_BLOCK + wid;

    const size_t row_base = (((size_t)b * N_SZ) + n) * N_SZ;
    const float4* yr4 = (const float4*)(Yr + row_base);
    const float4* yi4 = (const float4*)(Yi + row_base);

    // ---- PREFETCH depth 2: first two k-iterations' Y loads ----
    const float4 a_p0 = yr4[lid];
    const float4 c_p0 = yi4[lid];
    const float4 a_p1 = yr4[lid + 32];
    const float4 c_p1 = yi4[lid + 32];

    // Hoist scalar epilogue params (overlap staging too)
    const float dw  = d3w[0];
    const float db  = d3b[0];
    const float b2v = b2[0];
    const size_t idx = (size_t)b * N_SZ + n;
    const float xpr_v = xpr[idx];
    const float xpi_v = xpi[idx];

    // ---- Stage x + MLP weights into shared via cp.async (no reg traffic) --
    {
        const float4* xr4 = (const float4*)(xr + (size_t)b * N_SZ);
        const float4* xi4 = (const float4*)(xi + (size_t)b * N_SZ);
        #pragma unroll
        for (int k = tid; k < N_SZ / 4; k += THREADS) {
            __pipeline_memcpy_async(&((float4*)sxr)[k], &xr4[k], 16);
            __pipeline_memcpy_async(&((float4*)sxi)[k], &xi4[k], 16);
        }
        if (tid < HID) {
            __pipeline_memcpy_async(&sw1[tid], &w1[tid], 4);
            __pipeline_memcpy_async(&sb1[tid], &b1[tid], 4);
            __pipeline_memcpy_async(&sw2[tid], &w2[tid], 4);
        }
        __pipeline_commit();
        __pipeline_wait_prior(0);
    }
    __syncthreads();

    const float4* sxr4 = (const float4*)sxr;
    const float4* sxi4 = (const float4*)sxi;

    float rr = 0.f, ii = 0.f, ri = 0.f, ir = 0.f, ss = 0.f;

    // ---- Consume the two prefetched iterations ----
    {
        float4 u = sxr4[lid];
        float4 v = sxi4[lid];
        rr = fmaf(a_p0.x, u.x, rr); rr = fmaf(a_p0.y, u.y, rr);
        rr = fmaf(a_p0.z, u.z, rr); rr = fmaf(a_p0.w, u.w, rr);
        ii = fmaf(c_p0.x, v.x, ii); ii = fmaf(c_p0.y, v.y, ii);
        ii = fmaf(c_p0.z, v.z, ii); ii = fmaf(c_p0.w, v.w, ii);
        ri = fmaf(a_p0.x, v.x, ri); ri = fmaf(a_p0.y, v.y, ri);
        ri = fmaf(a_p0.z, v.z, ri); ri = fmaf(a_p0.w, v.w, ri);
        ir = fmaf(c_p0.x, u.x, ir); ir = fmaf(c_p0.y, u.y, ir);
        ir = fmaf(c_p0.z, u.z, ir); ir = fmaf(c_p0.w, u.w, ir);
        ss = fmaf(u.x, u.x, ss); ss = fmaf(u.y, u.y, ss);
        ss = fmaf(u.z, u.z, ss); ss = fmaf(u.w, u.w, ss);
        ss = fmaf(v.x, v.x, ss); ss = fmaf(v.y, v.y, ss);
        ss = fmaf(v.z, v.z, ss); ss = fmaf(v.w, v.w, ss);
    }
    {
        float4 u = sxr4[lid + 32];
        float4 v = sxi4[lid + 32];
        rr = fmaf(a_p1.x, u.x, rr); rr = fmaf(a_p1.y, u.y, rr);
        rr = fmaf(a_p1.z, u.z, rr); rr = fmaf(a_p1.w, u.w, rr);
        ii = fmaf(c_p1.x, v.x, ii); ii = fmaf(c_p1.y, v.y, ii);
        ii = fmaf(c_p1.z, v.z, ii); ii = fmaf(c_p1.w, v.w, ii);
        ri = fmaf(a_p1.x, v.x, ri); ri = fmaf(a_p1.y, v.y, ri);
        ri = fmaf(a_p1.z, v.z, ri); ri = fmaf(a_p1.w, v.w, ri);
        ir = fmaf(c_p1.x, u.x, ir); ir = fmaf(c_p1.y, u.y, ir);
        ir = fmaf(c_p1.z, u.z, ir); ir = fmaf(c_p1.w, u.w, ir);
        ss = fmaf(u.x, u.x, ss); ss = fmaf(u.y, u.y, ss);
        ss = fmaf(u.z, u.z, ss); ss = fmaf(u.w, u.w, ss);
        ss = fmaf(v.x, v.x, ss); ss = fmaf(v.y, v.y, ss);
        ss = fmaf(v.z, v.z, ss); ss = fmaf(v.w, v.w, ss);
    }

    // ---- Remaining 14 iterations, fully unrolled ----
    #pragma unroll 14
    for (int k = lid + 64; k < N_SZ / 4; k += 32) {
        float4 a = yr4[k];
        float4 c = yi4[k];
        float4 u = sxr4[k];
        float4 v = sxi4[k];
        rr = fmaf(a.x, u.x, rr); rr = fmaf(a.y, u.y, rr);
        rr = fmaf(a.z, u.z, rr); rr = fmaf(a.w, u.w, rr);
        ii = fmaf(c.x, v.x, ii); ii = fmaf(c.y, v.y, ii);
        ii = fmaf(c.z, v.z, ii); ii = fmaf(c.w, v.w, ii);
        ri = fmaf(a.x, v.x, ri); ri = fmaf(a.y, v.y, ri);
        ri = fmaf(a.z, v.z, ri); ri = fmaf(a.w, v.w, ri);
        ir = fmaf(c.x, u.x, ir); ir = fmaf(c.y, u.y, ir);
        ir = fmaf(c.z, u.z, ir); ir = fmaf(c.w, u.w, ir);
        ss = fmaf(u.x, u.x, ss); ss = fmaf(u.y, u.y, ss);
        ss = fmaf(u.z, u.z, ss); ss = fmaf(u.w, u.w, ss);
        ss = fmaf(v.x, v.x, ss); ss = fmaf(v.y, v.y, ss);
        ss = fmaf(v.z, v.z, ss); ss = fmaf(v.w, v.w, ss);
    }

    // butterfly reduce all five accumulators -> every lane has full sums
    #pragma unroll
    for (int off = 16; off > 0; off >>= 1) {
        rr += __shfl_xor_sync(0xFFFFFFFFu, rr, off);
        ii += __shfl_xor_sync(0xFFFFFFFFu, ii, off);
        ri += __shfl_xor_sync(0xFFFFFFFFu, ri, off);
        ir += __shfl_xor_sync(0xFFFFFFFFu, ir, off);
        ss += __shfl_xor_sync(0xFFFFFFFFu, ss, off);
    }

    // ---- Epilogue (per-warp; no cross-warp communication needed) ----
    const float sc = -(LAMBDA * LAMBDA) * (1.0f - ss / (float)N_SZ);

    float x1r = fmaf(LAMBDA * (rr - ii), dw, db);
    float x1i = fmaf(LAMBDA * (ri + ir), dw, db);
    x1r = fmaf(sc, xpr_v, x1r);
    x1i = fmaf(sc, xpi_v, x1i);

    const float xabs = sqrtf(x1r * x1r + x1i * x1i);

    // MLP: 256 hidden units, 8 per lane
    float partial = 0.f;
    #pragma unroll
    for (int j = lid; j < HID; j += 32) {
        float h = fmaxf(fmaf(xabs, sw1[j], sb1[j]), 0.f);
        partial = fmaf(h, sw2[j], partial);
    }
    #pragma unroll
    for (int off = 16; off > 0; off >>= 1)
        partial += __shfl_xor_sync(0xFFFFFFFFu, partial, off);

    if (lid == 0) {
        float g = tanhf(partial + b2v);
        float q = g / fmaxf(xabs, 1e-12f);
        out[idx] = x1r * q;                          // real part
        out[(size_t)B_SZ * N_SZ + idx] = x1i * q;    // imag part
    }
}

extern "C" void kernel_launch(void* const* d_in, const int* in_sizes, int n_in,
                              void* d_out, int out_size) {
    const float* Yr  = (const float*)d_in[0];
    const float* Yi  = (const float*)d_in[1];
    const float* xr  = (const float*)d_in[2];
    const float* xi  = (const float*)d_in[3];
    const float* xpr = (const float*)d_in[4];
    const float* xpi = (const float*)d_in[5];
    const float* d3w = (const float*)d_in[6];
    const float* d3b = (const float*)d_in[7];
    const float* w1  = (const float*)d_in[8];
    const float* b1  = (const float*)d_in[9];
    const float* w2  = (const float*)d_in[10];
    const float* b2  = (const float*)d_in[11];
    float* out = (float*)d_out;

    dim3 grid(N_SZ / WARPS_PER_BLOCK, B_SZ);
    fused_kernel<<<grid, THREADS>>>(Yr, Yi, xr, xi, xpr, xpi,
                                    d3w, d3b, w1, b1, w2, b2, out);
}